// round 6
// baseline (speedup 1.0000x reference)
#include <cuda_runtime.h>
#include <cstdint>

// ----------------------------------------------------------------------------
// BlockSparseLinear: y[8192,4096] = x[8192,4096] @ W^T + bias
// W block-sparse: 64 row-blocks x 16 nonzero 64x64 col-blocks each.
//
// R5: software-pipelined cp.async double buffering. K streamed in 32 chunks of
// 32 (16 col-blocks x 2 halves); chunk kc+1 staged via cp.async.cg while chunk
// kc computes. tf32 rounding (cvt.rna, unbiased) moved to fragment-load time.
// CTA: 256 tokens x 64 outs, 8 warps (warp tile 32x64), 2 CTAs/SM.
// ----------------------------------------------------------------------------

static constexpr int IN_F  = 4096;
static constexpr int OUT_F = 4096;
static constexpr int BLKSZ = 64;
static constexpr int KBLK  = 16;
static constexpr int BM    = 256;          // tokens per CTA
static constexpr int KC    = 32;           // K chunk (half a col-block)
static constexpr int NCHUNK = KBLK * 2;    // 32
static constexpr int NTHREADS = 256;       // 8 warps
static constexpr int CPAD  = 36;           // padded chunk row stride (floats, 144B)

static constexpr int A_BUF = BM * CPAD;       // 9216 floats / buffer
static constexpr int B_BUF = BLKSZ * CPAD;    // 2304 floats / buffer
static constexpr int DYN_SMEM = 2 * (A_BUF + B_BUF) * 4;   // 92160 B

static __device__ __forceinline__ uint32_t f2tf(float f) {
    uint32_t u;
    asm("cvt.rna.tf32.f32 %0, %1;" : "=r"(u) : "f"(f));
    return u;
}

static __device__ __forceinline__ void cp16(uint32_t dst_smem, const void* src) {
    asm volatile("cp.async.cg.shared.global [%0], [%1], 16;"
                 :: "r"(dst_smem), "l"(src) : "memory");
}
static __device__ __forceinline__ void cp_commit() {
    asm volatile("cp.async.commit_group;" ::: "memory");
}
template <int N>
static __device__ __forceinline__ void cp_wait() {
    asm volatile("cp.async.wait_group %0;" :: "n"(N) : "memory");
}

static __device__ __forceinline__ void mma_tf32_16x8x8(
    float& d0, float& d1, float& d2, float& d3,
    uint32_t a0, uint32_t a1, uint32_t a2, uint32_t a3,
    uint32_t b0, uint32_t b1)
{
    asm volatile(
        "mma.sync.aligned.m16n8k8.row.col.f32.tf32.tf32.f32 "
        "{%0,%1,%2,%3}, {%4,%5,%6,%7}, {%8,%9}, {%0,%1,%2,%3};"
        : "+f"(d0), "+f"(d1), "+f"(d2), "+f"(d3)
        : "r"(a0), "r"(a1), "r"(a2), "r"(a3), "r"(b0), "r"(b1));
}

// ----------------------------------------------------------------------------
__global__ __launch_bounds__(NTHREADS, 2)
void bsl_pipe_kernel(const float* __restrict__ x,
                     const float* __restrict__ w,
                     const float* __restrict__ bias,
                     const int*   __restrict__ col_idx,
                     float*       __restrict__ out)
{
    extern __shared__ float smem[];
    float* As = smem;                    // 2 x [BM][CPAD]
    float* Bs = smem + 2 * A_BUF;        // 2 x [64][CPAD]

    const int tid  = threadIdx.x;
    const int wid  = tid >> 5;
    const int lane = tid & 31;
    const int g    = lane >> 2;          // 0..7
    const int cq   = lane & 3;           // 0..3

    const int rb   = blockIdx.x;
    const int tok0 = blockIdx.y * BM;
    const int warp_m = wid * 32;

    // Cache the 16 column indices in registers (uniform across CTA).
    int colreg[KBLK];
    #pragma unroll
    for (int i = 0; i < KBLK; ++i) colreg[i] = __ldg(col_idx + rb * KBLK + i);

    const uint32_t As_u = (uint32_t)__cvta_generic_to_shared(As);
    const uint32_t Bs_u = (uint32_t)__cvta_generic_to_shared(Bs);

    // Per-thread staging geometry (16B granules, 8 per 32-float row).
    const int sa_row0 = tid >> 3;        // A: rows tid/8 + 32*i
    const int sc16    = (tid & 7) << 2;  // float offset 0,4,...,28

    float acc[2][8][4];
    #pragma unroll
    for (int mt = 0; mt < 2; ++mt)
        #pragma unroll
        for (int nt = 0; nt < 8; ++nt)
            #pragma unroll
            for (int r = 0; r < 4; ++r) acc[mt][nt][r] = 0.0f;

    // ---- stage one chunk (kc) into buffer buf ----
    auto stage = [&](int kc, int buf) {
        const int cb = kc >> 1;
        const int h  = kc & 1;
        const int c  = colreg[cb];
        const float* xsrc = x + (size_t)tok0 * IN_F + (size_t)c * BLKSZ + h * KC;
        const uint32_t Ab = As_u + (uint32_t)(buf * A_BUF) * 4u;
        #pragma unroll
        for (int i = 0; i < 8; ++i) {                 // 256 rows x 8 granules
            const int row = sa_row0 + i * 32;
            cp16(Ab + (uint32_t)(row * CPAD + sc16) * 4u,
                 xsrc + (size_t)row * IN_F + sc16);
        }
        const float* wsrc = w + ((size_t)rb * KBLK + cb) * (BLKSZ * BLKSZ) + h * KC;
        const uint32_t Bb = Bs_u + (uint32_t)(buf * B_BUF) * 4u;
        #pragma unroll
        for (int i = 0; i < 2; ++i) {                 // 64 rows x 8 granules
            const int row = sa_row0 + i * 32;
            cp16(Bb + (uint32_t)(row * CPAD + sc16) * 4u,
                 wsrc + (size_t)row * BLKSZ + sc16);
        }
        cp_commit();
    };

    stage(0, 0);

    for (int kc = 0; kc < NCHUNK; ++kc) {
        const int buf = kc & 1;
        if (kc + 1 < NCHUNK) {
            stage(kc + 1, buf ^ 1);
            cp_wait<1>();     // chunk kc's group done; kc+1 still in flight
        } else {
            cp_wait<0>();
        }
        __syncthreads();

        const uint32_t* Au = reinterpret_cast<const uint32_t*>(As + buf * A_BUF);
        const uint32_t* Bu = reinterpret_cast<const uint32_t*>(Bs + buf * B_BUF);

        #pragma unroll
        for (int k0 = 0; k0 < KC; k0 += 8) {
            uint32_t b[8][2];
            #pragma unroll
            for (int nt = 0; nt < 8; ++nt) {
                const int n0 = nt * 8 + g;
                b[nt][0] = f2tf(__uint_as_float(Bu[n0 * CPAD + k0 + cq    ]));
                b[nt][1] = f2tf(__uint_as_float(Bu[n0 * CPAD + k0 + cq + 4]));
            }
            uint32_t a[2][4];
            #pragma unroll
            for (int mt = 0; mt < 2; ++mt) {
                const int r0 = warp_m + mt * 16 + g;
                a[mt][0] = f2tf(__uint_as_float(Au[(r0    ) * CPAD + k0 + cq    ]));
                a[mt][1] = f2tf(__uint_as_float(Au[(r0 + 8) * CPAD + k0 + cq    ]));
                a[mt][2] = f2tf(__uint_as_float(Au[(r0    ) * CPAD + k0 + cq + 4]));
                a[mt][3] = f2tf(__uint_as_float(Au[(r0 + 8) * CPAD + k0 + cq + 4]));
            }
            #pragma unroll
            for (int mt = 0; mt < 2; ++mt)
                #pragma unroll
                for (int nt = 0; nt < 8; ++nt)
                    mma_tf32_16x8x8(acc[mt][nt][0], acc[mt][nt][1],
                                    acc[mt][nt][2], acc[mt][nt][3],
                                    a[mt][0], a[mt][1], a[mt][2], a[mt][3],
                                    b[nt][0], b[nt][1]);
        }
        __syncthreads();   // buffer safe to overwrite by stage(kc+2)
    }

    // ---- epilogue: +bias, store fp32 ----
    const float* bsrc = bias + rb * BLKSZ;
    #pragma unroll
    for (int mt = 0; mt < 2; ++mt) {
        const int row0 = tok0 + warp_m + mt * 16 + g;
        #pragma unroll
        for (int nt = 0; nt < 8; ++nt) {
            const int col = nt * 8 + 2 * cq;
            const float2 bv = *reinterpret_cast<const float2*>(bsrc + col);
            float* d0 = out + (size_t)row0 * OUT_F + rb * BLKSZ + col;
            float* d1 = out + (size_t)(row0 + 8) * OUT_F + rb * BLKSZ + col;
            float2 o0, o1;
            o0.x = acc[mt][nt][0] + bv.x;
            o0.y = acc[mt][nt][1] + bv.y;
            o1.x = acc[mt][nt][2] + bv.x;
            o1.y = acc[mt][nt][3] + bv.y;
            *reinterpret_cast<float2*>(d0) = o0;
            *reinterpret_cast<float2*>(d1) = o1;
        }
    }
}

// ----------------------------------------------------------------------------
extern "C" void kernel_launch(void* const* d_in, const int* in_sizes, int n_in,
                              void* d_out, int out_size)
{
    const float* x = nullptr;
    const float* w = nullptr;
    const float* bias = nullptr;
    const int* row_idx = nullptr;
    const int* col_idx = nullptr;

    for (int i = 0; i < n_in; ++i) {
        long s = (long)in_sizes[i];
        if (s == 8192L * 4096L)          x = (const float*)d_in[i];
        else if (s == 1024L * 64L * 64L) w = (const float*)d_in[i];
        else if (s == 4096L)             bias = (const float*)d_in[i];
        else if (s == 1024L) {
            if (!row_idx) row_idx = (const int*)d_in[i];
            else          col_idx = (const int*)d_in[i];
        }
    }
    if (!x || !w || !bias || !col_idx) {   // positional fallback
        x       = (const float*)d_in[0];
        w       = (const float*)d_in[1];
        bias    = (const float*)d_in[2];
        row_idx = (const int*)d_in[3];
        col_idx = (const int*)d_in[4];
    }
    (void)row_idx; (void)out_size;

    cudaFuncSetAttribute(bsl_pipe_kernel,
                         cudaFuncAttributeMaxDynamicSharedMemorySize, DYN_SMEM);

    dim3 grid(64, 32);   // x = row-block (fast), y = token tile
    bsl_pipe_kernel<<<grid, NTHREADS, DYN_SMEM>>>(x, w, bias, col_idx, (float*)d_out);
}

// round 8
// speedup vs baseline: 1.1501x; 1.1501x over previous
#include <cuda_runtime.h>
#include <cstdint>

// ----------------------------------------------------------------------------
// BlockSparseLinear: y[8192,4096] = x[8192,4096] @ W^T + bias
// W block-sparse: 64 row-blocks x 16 nonzero 64x64 col-blocks each.
//
// R6: attack barrier-exposed time (tensor pinned at 47% across R3-R5 while
// tensor-active time == rt=8 floor of ~230us).
//   - 3-stage cp.async ring, ONE __syncthreads per K-chunk (32 chunks of K=32)
//   - CTA: 128 tokens x 64 outs, 4 warps (warp tile 32x64)
//   - XOR-swizzled 128B rows (no padding) -> 73.7KB smem -> 3 CTAs/SM
//   - tf32 rounding (cvt.rna, unbiased) at fragment-load time
// ----------------------------------------------------------------------------

static constexpr int IN_F  = 4096;
static constexpr int OUT_F = 4096;
static constexpr int BLKSZ = 64;
static constexpr int KBLK  = 16;
static constexpr int BM    = 128;          // tokens per CTA
static constexpr int KC    = 32;           // K per chunk (half a col-block)
static constexpr int NCHUNK = KBLK * 2;    // 32
static constexpr int NSTAGE = 3;
static constexpr int NTHREADS = 128;       // 4 warps

static constexpr int A_BUF = BM * KC;          // 4096 floats
static constexpr int B_BUF = BLKSZ * KC;       // 2048 floats
static constexpr int STAGE_FLOATS = A_BUF + B_BUF;              // 6144
static constexpr int DYN_SMEM = NSTAGE * STAGE_FLOATS * 4;      // 73728 B

static __device__ __forceinline__ uint32_t f2tf(float f) {
    uint32_t u;
    asm("cvt.rna.tf32.f32 %0, %1;" : "=r"(u) : "f"(f));
    return u;
}

static __device__ __forceinline__ void cp16(uint32_t dst_smem, const void* src) {
    asm volatile("cp.async.cg.shared.global [%0], [%1], 16;"
                 :: "r"(dst_smem), "l"(src) : "memory");
}
static __device__ __forceinline__ void cp_commit() {
    asm volatile("cp.async.commit_group;" ::: "memory");
}
template <int N>
static __device__ __forceinline__ void cp_wait() {
    asm volatile("cp.async.wait_group %0;" :: "n"(N) : "memory");
}

static __device__ __forceinline__ void mma_tf32_16x8x8(
    float& d0, float& d1, float& d2, float& d3,
    uint32_t a0, uint32_t a1, uint32_t a2, uint32_t a3,
    uint32_t b0, uint32_t b1)
{
    asm volatile(
        "mma.sync.aligned.m16n8k8.row.col.f32.tf32.tf32.f32 "
        "{%0,%1,%2,%3}, {%4,%5,%6,%7}, {%8,%9}, {%0,%1,%2,%3};"
        : "+f"(d0), "+f"(d1), "+f"(d2), "+f"(d3)
        : "r"(a0), "r"(a1), "r"(a2), "r"(a3), "r"(b0), "r"(b1));
}

// row-major [rows][KC] with granule swizzle: float4-granule q of row r lands at
// float offset r*KC + ((q ^ (r & 7)) << 2). Conflict-free for both cp.async
// stores and m16n8k8 fragment loads (banks 4*(q^g)+cq distinct across g).
static __device__ __forceinline__ int swz(int row, int kk) {
    // kk = element column 0..31; granule = kk>>2, offset = kk&3
    return row * KC + ((((kk >> 2) ^ (row & 7)) << 2) | (kk & 3));
}

// ----------------------------------------------------------------------------
__global__ __launch_bounds__(NTHREADS, 3)
void bsl_ring_kernel(const float* __restrict__ x,
                     const float* __restrict__ w,
                     const float* __restrict__ bias,
                     const int*   __restrict__ col_idx,
                     float*       __restrict__ out)
{
    extern __shared__ float smem[];

    const int tid  = threadIdx.x;
    const int wid  = tid >> 5;
    const int lane = tid & 31;
    const int g    = lane >> 2;          // 0..7
    const int cq   = lane & 3;           // 0..3

    const int rb   = blockIdx.x;
    const int tok0 = blockIdx.y * BM;
    const int warp_m = wid * 32;

    // Cache the 16 column indices in registers (uniform across CTA).
    int colreg[KBLK];
    #pragma unroll
    for (int i = 0; i < KBLK; ++i) colreg[i] = __ldg(col_idx + rb * KBLK + i);

    const uint32_t smem_u = (uint32_t)__cvta_generic_to_shared(smem);

    // Staging geometry: granule q = tid&7 (16B), base row tid>>3 (16 rows/pass).
    const int srow = tid >> 3;
    const int sq   = tid & 7;

    float acc[2][8][4];
    #pragma unroll
    for (int mt = 0; mt < 2; ++mt)
        #pragma unroll
        for (int nt = 0; nt < 8; ++nt)
            #pragma unroll
            for (int r = 0; r < 4; ++r) acc[mt][nt][r] = 0.0f;

    // ---- stage chunk kc into ring slot (kc % NSTAGE) ----
    auto stage = [&](int kc) {
        const int s  = kc % NSTAGE;
        const int cb = kc >> 1;
        const int h  = kc & 1;
        const int c  = colreg[cb];
        const uint32_t Ab = smem_u + (uint32_t)(s * STAGE_FLOATS) * 4u;
        const uint32_t Bb = Ab + (uint32_t)A_BUF * 4u;

        const float* xsrc = x + (size_t)tok0 * IN_F + (size_t)c * BLKSZ + h * KC;
        #pragma unroll
        for (int i = 0; i < 8; ++i) {            // 128 rows, 16 per pass
            const int row = srow + i * 16;
            cp16(Ab + (uint32_t)(row * KC + (((sq ^ (row & 7)) << 2))) * 4u,
                 xsrc + (size_t)row * IN_F + sq * 4);
        }
        const float* wsrc = w + ((size_t)rb * KBLK + cb) * (BLKSZ * BLKSZ) + h * KC;
        #pragma unroll
        for (int i = 0; i < 4; ++i) {            // 64 rows
            const int row = srow + i * 16;
            cp16(Bb + (uint32_t)(row * KC + (((sq ^ (row & 7)) << 2))) * 4u,
                 wsrc + (size_t)row * BLKSZ + sq * 4);
        }
        cp_commit();
    };

    // Prologue: stage chunks 0..NSTAGE-2 (keeps NSTAGE-1 groups in flight).
    stage(0);
    stage(1);

    for (int kc = 0; kc < NCHUNK; ++kc) {
        // Exactly NSTAGE-1 groups pending here (tail pads with empty commits),
        // so wait<NSTAGE-2> == "chunk kc complete".
        cp_wait<NSTAGE - 2>();
        __syncthreads();   // publish chunk kc to all warps; ring slot (kc+2)%3
                           // now provably consumed by every warp (at kc-1).

        if (kc + NSTAGE - 1 < NCHUNK) stage(kc + NSTAGE - 1);
        else                          cp_commit();   // empty group: keep count

        const int s = kc % NSTAGE;
        const uint32_t* Au = reinterpret_cast<const uint32_t*>(smem + s * STAGE_FLOATS);
        const uint32_t* Bu = Au + A_BUF;

        #pragma unroll
        for (int k0 = 0; k0 < KC; k0 += 8) {
            uint32_t b[8][2];
            #pragma unroll
            for (int nt = 0; nt < 8; ++nt) {
                const int n0 = nt * 8 + g;
                b[nt][0] = f2tf(__uint_as_float(Bu[swz(n0, k0 + cq)]));
                b[nt][1] = f2tf(__uint_as_float(Bu[swz(n0, k0 + cq + 4)]));
            }
            uint32_t a[2][4];
            #pragma unroll
            for (int mt = 0; mt < 2; ++mt) {
                const int r0 = warp_m + mt * 16 + g;
                a[mt][0] = f2tf(__uint_as_float(Au[swz(r0,     k0 + cq)]));
                a[mt][1] = f2tf(__uint_as_float(Au[swz(r0 + 8, k0 + cq)]));
                a[mt][2] = f2tf(__uint_as_float(Au[swz(r0,     k0 + cq + 4)]));
                a[mt][3] = f2tf(__uint_as_float(Au[swz(r0 + 8, k0 + cq + 4)]));
            }
            #pragma unroll
            for (int mt = 0; mt < 2; ++mt)
                #pragma unroll
                for (int nt = 0; nt < 8; ++nt)
                    mma_tf32_16x8x8(acc[mt][nt][0], acc[mt][nt][1],
                                    acc[mt][nt][2], acc[mt][nt][3],
                                    a[mt][0], a[mt][1], a[mt][2], a[mt][3],
                                    b[nt][0], b[nt][1]);
        }
        // NOTE: no trailing __syncthreads — ring spacing (NSTAGE=3) plus the
        // top-of-loop barrier provides the reuse guarantee.
    }

    // ---- epilogue: +bias, store fp32 ----
    const float* bsrc = bias + rb * BLKSZ;
    #pragma unroll
    for (int mt = 0; mt < 2; ++mt) {
        const int row0 = tok0 + warp_m + mt * 16 + g;
        #pragma unroll
        for (int nt = 0; nt < 8; ++nt) {
            const int col = nt * 8 + 2 * cq;
            const float2 bv = *reinterpret_cast<const float2*>(bsrc + col);
            float* d0 = out + (size_t)row0 * OUT_F + rb * BLKSZ + col;
            float* d1 = out + (size_t)(row0 + 8) * OUT_F + rb * BLKSZ + col;
            float2 o0, o1;
            o0.x = acc[mt][nt][0] + bv.x;
            o0.y = acc[mt][nt][1] + bv.y;
            o1.x = acc[mt][nt][2] + bv.x;
            o1.y = acc[mt][nt][3] + bv.y;
            *reinterpret_cast<float2*>(d0) = o0;
            *reinterpret_cast<float2*>(d1) = o1;
        }
    }
}

// ----------------------------------------------------------------------------
extern "C" void kernel_launch(void* const* d_in, const int* in_sizes, int n_in,
                              void* d_out, int out_size)
{
    const float* x = nullptr;
    const float* w = nullptr;
    const float* bias = nullptr;
    const int* row_idx = nullptr;
    const int* col_idx = nullptr;

    for (int i = 0; i < n_in; ++i) {
        long s = (long)in_sizes[i];
        if (s == 8192L * 4096L)          x = (const float*)d_in[i];
        else if (s == 1024L * 64L * 64L) w = (const float*)d_in[i];
        else if (s == 4096L)             bias = (const float*)d_in[i];
        else if (s == 1024L) {
            if (!row_idx) row_idx = (const int*)d_in[i];
            else          col_idx = (const int*)d_in[i];
        }
    }
    if (!x || !w || !bias || !col_idx) {   // positional fallback
        x       = (const float*)d_in[0];
        w       = (const float*)d_in[1];
        bias    = (const float*)d_in[2];
        row_idx = (const int*)d_in[3];
        col_idx = (const int*)d_in[4];
    }
    (void)row_idx; (void)out_size;

    cudaFuncSetAttribute(bsl_ring_kernel,
                         cudaFuncAttributeMaxDynamicSharedMemorySize, DYN_SMEM);

    dim3 grid(64, 64);   // x = row-block (fast, shares x via L2), y = token tile
    bsl_ring_kernel<<<grid, NTHREADS, DYN_SMEM>>>(x, w, bias, col_idx, (float*)d_out);
}

// round 9
// speedup vs baseline: 1.2942x; 1.1252x over previous
#include <cuda_runtime.h>
#include <cstdint>

// ----------------------------------------------------------------------------
// BlockSparseLinear: y[8192,4096] = x[8192,4096] @ W^T + bias
// W block-sparse: 64 row-blocks x 16 nonzero 64x64 col-blocks each.
//
// R8: inner loop was issue-bound (alu 36.8% from 24 cvt.rna/kstep). A 7us
// pre-pass converts W (16MB) to tf32 bits once into __device__ scratch; the
// main kernel's B-fragments are plain LDS (16 of 24 cvts gone). A keeps
// load-time cvt.rna (identical arithmetic -> rel_err must stay 2.935e-4).
// Structure otherwise = R6: 3-stage cp.async ring, one barrier per chunk,
// CTA 128 tokens x 64 outs, 4 warps, XOR-swizzled rows, 3 CTAs/SM.
// ----------------------------------------------------------------------------

static constexpr int IN_F  = 4096;
static constexpr int OUT_F = 4096;
static constexpr int BLKSZ = 64;
static constexpr int KBLK  = 16;
static constexpr int BM    = 128;          // tokens per CTA
static constexpr int KC    = 32;           // K per chunk (half a col-block)
static constexpr int NCHUNK = KBLK * 2;    // 32
static constexpr int NSTAGE = 3;
static constexpr int NTHREADS = 128;       // 4 warps

static constexpr int A_BUF = BM * KC;          // 4096 floats
static constexpr int B_BUF = BLKSZ * KC;       // 2048 floats
static constexpr int STAGE_FLOATS = A_BUF + B_BUF;              // 6144
static constexpr int DYN_SMEM = NSTAGE * STAGE_FLOATS * 4;      // 73728 B

// Pre-converted W (tf32 bits), same layout as w: [1024][64][64].
static constexpr int W_ELEMS = 1024 * 64 * 64;
__device__ uint32_t g_wtf[W_ELEMS];

static __device__ __forceinline__ uint32_t f2tf(float f) {
    uint32_t u;
    asm("cvt.rna.tf32.f32 %0, %1;" : "=r"(u) : "f"(f));
    return u;
}

static __device__ __forceinline__ void cp16(uint32_t dst_smem, const void* src) {
    asm volatile("cp.async.cg.shared.global [%0], [%1], 16;"
                 :: "r"(dst_smem), "l"(src) : "memory");
}
static __device__ __forceinline__ void cp_commit() {
    asm volatile("cp.async.commit_group;" ::: "memory");
}
template <int N>
static __device__ __forceinline__ void cp_wait() {
    asm volatile("cp.async.wait_group %0;" :: "n"(N) : "memory");
}

static __device__ __forceinline__ void mma_tf32_16x8x8(
    float& d0, float& d1, float& d2, float& d3,
    uint32_t a0, uint32_t a1, uint32_t a2, uint32_t a3,
    uint32_t b0, uint32_t b1)
{
    asm volatile(
        "mma.sync.aligned.m16n8k8.row.col.f32.tf32.tf32.f32 "
        "{%0,%1,%2,%3}, {%4,%5,%6,%7}, {%8,%9}, {%0,%1,%2,%3};"
        : "+f"(d0), "+f"(d1), "+f"(d2), "+f"(d3)
        : "r"(a0), "r"(a1), "r"(a2), "r"(a3), "r"(b0), "r"(b1));
}

// row-major [rows][KC] with float4-granule swizzle: granule q of row r lands
// at r*KC + ((q ^ (r & 7)) << 2). Conflict-free for cp.async stores and for
// m16n8k8 fragment loads (banks 4*(q^g)+cq distinct across g).
static __device__ __forceinline__ int swz(int row, int kk) {
    return row * KC + ((((kk >> 2) ^ (row & 7)) << 2) | (kk & 3));
}

// ---- pre-pass: W fp32 -> tf32 bits (16MB, ~7us) ----------------------------
__global__ __launch_bounds__(256)
void convert_w_kernel(const float* __restrict__ w)
{
    const int i = blockIdx.x * 256 + threadIdx.x;   // float4 index
    const float4* src = reinterpret_cast<const float4*>(w);
    uint4* dst = reinterpret_cast<uint4*>(g_wtf);
    float4 v = src[i];
    uint4 t;
    t.x = f2tf(v.x); t.y = f2tf(v.y); t.z = f2tf(v.z); t.w = f2tf(v.w);
    dst[i] = t;
}

// ----------------------------------------------------------------------------
__global__ __launch_bounds__(NTHREADS, 3)
void bsl_ring_kernel(const float* __restrict__ x,
                     const float* __restrict__ bias,
                     const int*   __restrict__ col_idx,
                     float*       __restrict__ out)
{
    extern __shared__ float smem[];

    const int tid  = threadIdx.x;
    const int wid  = tid >> 5;
    const int lane = tid & 31;
    const int g    = lane >> 2;          // 0..7
    const int cq   = lane & 3;           // 0..3

    const int rb   = blockIdx.x;
    const int tok0 = blockIdx.y * BM;
    const int warp_m = wid * 32;

    int colreg[KBLK];
    #pragma unroll
    for (int i = 0; i < KBLK; ++i) colreg[i] = __ldg(col_idx + rb * KBLK + i);

    const uint32_t smem_u = (uint32_t)__cvta_generic_to_shared(smem);

    const int srow = tid >> 3;           // staging: 16 rows per pass
    const int sq   = tid & 7;            // float4 granule within row

    float acc[2][8][4];
    #pragma unroll
    for (int mt = 0; mt < 2; ++mt)
        #pragma unroll
        for (int nt = 0; nt < 8; ++nt)
            #pragma unroll
            for (int r = 0; r < 4; ++r) acc[mt][nt][r] = 0.0f;

    auto stage = [&](int kc) {
        const int s  = kc % NSTAGE;
        const int cb = kc >> 1;
        const int h  = kc & 1;
        const int c  = colreg[cb];
        const uint32_t Ab = smem_u + (uint32_t)(s * STAGE_FLOATS) * 4u;
        const uint32_t Bb = Ab + (uint32_t)A_BUF * 4u;

        const float* xsrc = x + (size_t)tok0 * IN_F + (size_t)c * BLKSZ + h * KC;
        #pragma unroll
        for (int i = 0; i < 8; ++i) {            // 128 rows
            const int row = srow + i * 16;
            cp16(Ab + (uint32_t)(row * KC + (((sq ^ (row & 7)) << 2))) * 4u,
                 xsrc + (size_t)row * IN_F + sq * 4);
        }
        const uint32_t* wsrc = g_wtf + ((size_t)rb * KBLK + cb) * (BLKSZ * BLKSZ) + h * KC;
        #pragma unroll
        for (int i = 0; i < 4; ++i) {            // 64 rows
            const int row = srow + i * 16;
            cp16(Bb + (uint32_t)(row * KC + (((sq ^ (row & 7)) << 2))) * 4u,
                 wsrc + (size_t)row * BLKSZ + sq * 4);
        }
        cp_commit();
    };

    stage(0);
    stage(1);

    for (int kc = 0; kc < NCHUNK; ++kc) {
        cp_wait<NSTAGE - 2>();
        __syncthreads();   // publish chunk kc; slot (kc+2)%3 consumed by all

        if (kc + NSTAGE - 1 < NCHUNK) stage(kc + NSTAGE - 1);
        else                          cp_commit();   // keep group count exact

        const int s = kc % NSTAGE;
        const uint32_t* Au = reinterpret_cast<const uint32_t*>(smem + s * STAGE_FLOATS);
        const uint32_t* Bu = Au + A_BUF;

        #pragma unroll
        for (int k0 = 0; k0 < KC; k0 += 8) {
            uint32_t b[8][2];
            #pragma unroll
            for (int nt = 0; nt < 8; ++nt) {      // pre-converted: plain LDS
                const int n0 = nt * 8 + g;
                b[nt][0] = Bu[swz(n0, k0 + cq)];
                b[nt][1] = Bu[swz(n0, k0 + cq + 4)];
            }
            uint32_t a[2][4];
            #pragma unroll
            for (int mt = 0; mt < 2; ++mt) {
                const int r0 = warp_m + mt * 16 + g;
                a[mt][0] = f2tf(__uint_as_float(Au[swz(r0,     k0 + cq)]));
                a[mt][1] = f2tf(__uint_as_float(Au[swz(r0 + 8, k0 + cq)]));
                a[mt][2] = f2tf(__uint_as_float(Au[swz(r0,     k0 + cq + 4)]));
                a[mt][3] = f2tf(__uint_as_float(Au[swz(r0 + 8, k0 + cq + 4)]));
            }
            #pragma unroll
            for (int mt = 0; mt < 2; ++mt)
                #pragma unroll
                for (int nt = 0; nt < 8; ++nt)
                    mma_tf32_16x8x8(acc[mt][nt][0], acc[mt][nt][1],
                                    acc[mt][nt][2], acc[mt][nt][3],
                                    a[mt][0], a[mt][1], a[mt][2], a[mt][3],
                                    b[nt][0], b[nt][1]);
        }
    }

    // ---- epilogue: +bias, store fp32 ----
    const float* bsrc = bias + rb * BLKSZ;
    #pragma unroll
    for (int mt = 0; mt < 2; ++mt) {
        const int row0 = tok0 + warp_m + mt * 16 + g;
        #pragma unroll
        for (int nt = 0; nt < 8; ++nt) {
            const int col = nt * 8 + 2 * cq;
            const float2 bv = *reinterpret_cast<const float2*>(bsrc + col);
            float* d0 = out + (size_t)row0 * OUT_F + rb * BLKSZ + col;
            float* d1 = out + (size_t)(row0 + 8) * OUT_F + rb * BLKSZ + col;
            float2 o0, o1;
            o0.x = acc[mt][nt][0] + bv.x;
            o0.y = acc[mt][nt][1] + bv.y;
            o1.x = acc[mt][nt][2] + bv.x;
            o1.y = acc[mt][nt][3] + bv.y;
            *reinterpret_cast<float2*>(d0) = o0;
            *reinterpret_cast<float2*>(d1) = o1;
        }
    }
}

// ----------------------------------------------------------------------------
extern "C" void kernel_launch(void* const* d_in, const int* in_sizes, int n_in,
                              void* d_out, int out_size)
{
    const float* x = nullptr;
    const float* w = nullptr;
    const float* bias = nullptr;
    const int* row_idx = nullptr;
    const int* col_idx = nullptr;

    for (int i = 0; i < n_in; ++i) {
        long s = (long)in_sizes[i];
        if (s == 8192L * 4096L)          x = (const float*)d_in[i];
        else if (s == 1024L * 64L * 64L) w = (const float*)d_in[i];
        else if (s == 4096L)             bias = (const float*)d_in[i];
        else if (s == 1024L) {
            if (!row_idx) row_idx = (const int*)d_in[i];
            else          col_idx = (const int*)d_in[i];
        }
    }
    if (!x || !w || !bias || !col_idx) {   // positional fallback
        x       = (const float*)d_in[0];
        w       = (const float*)d_in[1];
        bias    = (const float*)d_in[2];
        row_idx = (const int*)d_in[3];
        col_idx = (const int*)d_in[4];
    }
    (void)row_idx; (void)out_size;

    // Pass 1: W -> tf32 bits (1048576 float4s).
    convert_w_kernel<<<W_ELEMS / 4 / 256, 256>>>(w);

    // Pass 2: main GEMM.
    cudaFuncSetAttribute(bsl_ring_kernel,
                         cudaFuncAttributeMaxDynamicSharedMemorySize, DYN_SMEM);
    dim3 grid(64, 64);   // x = row-block (fast, shares x via L2), y = token tile
    bsl_ring_kernel<<<grid, NTHREADS, DYN_SMEM>>>(x, bias, col_idx, (float*)d_out);
}

// round 10
// speedup vs baseline: 1.3167x; 1.0174x over previous
#include <cuda_runtime.h>
#include <cstdint>

// ----------------------------------------------------------------------------
// BlockSparseLinear: y[8192,4096] = x[8192,4096] @ W^T + bias
// W block-sparse: 64 row-blocks x 16 nonzero 64x64 col-blocks each.
//
// R9: fragment loads via ldmatrix.x4 (24 LDS.32 -> 6 LDSM per k-step/warp).
// The tf32 m16n8k8 fragment mapping (thread t <- word t&3 of row t>>2 of an
// 8x16B tile) equals ldmatrix.m8n8.b16 distribution over 32-bit words.
// A loads raw x bits then cvt.rna on regs (identical arithmetic); B comes
// from the pre-converted tf32 W scratch (no cvt).
// Structure = R8: 3-stage cp.async ring, one barrier/chunk, CTA 128x64,
// 4 warps, XOR-swizzled rows, 3 CTAs/SM.
// ----------------------------------------------------------------------------

static constexpr int IN_F  = 4096;
static constexpr int OUT_F = 4096;
static constexpr int BLKSZ = 64;
static constexpr int KBLK  = 16;
static constexpr int BM    = 128;          // tokens per CTA
static constexpr int KC    = 32;           // K per chunk (half a col-block)
static constexpr int NCHUNK = KBLK * 2;    // 32
static constexpr int NSTAGE = 3;
static constexpr int NTHREADS = 128;       // 4 warps

static constexpr int A_BUF = BM * KC;          // 4096 floats
static constexpr int B_BUF = BLKSZ * KC;       // 2048 floats
static constexpr int STAGE_FLOATS = A_BUF + B_BUF;              // 6144
static constexpr int DYN_SMEM = NSTAGE * STAGE_FLOATS * 4;      // 73728 B

// Pre-converted W (tf32 bits), same layout as w: [1024][64][64].
static constexpr int W_ELEMS = 1024 * 64 * 64;
__device__ uint32_t g_wtf[W_ELEMS];

static __device__ __forceinline__ uint32_t f2tf(float f) {
    uint32_t u;
    asm("cvt.rna.tf32.f32 %0, %1;" : "=r"(u) : "f"(f));
    return u;
}

static __device__ __forceinline__ void cp16(uint32_t dst_smem, const void* src) {
    asm volatile("cp.async.cg.shared.global [%0], [%1], 16;"
                 :: "r"(dst_smem), "l"(src) : "memory");
}
static __device__ __forceinline__ void cp_commit() {
    asm volatile("cp.async.commit_group;" ::: "memory");
}
template <int N>
static __device__ __forceinline__ void cp_wait() {
    asm volatile("cp.async.wait_group %0;" :: "n"(N) : "memory");
}

static __device__ __forceinline__ void ldsm4(uint32_t& r0, uint32_t& r1,
                                             uint32_t& r2, uint32_t& r3,
                                             uint32_t addr) {
    asm volatile("ldmatrix.sync.aligned.m8n8.x4.shared.b16 {%0,%1,%2,%3}, [%4];"
                 : "=r"(r0), "=r"(r1), "=r"(r2), "=r"(r3) : "r"(addr));
}

static __device__ __forceinline__ void mma_tf32_16x8x8(
    float& d0, float& d1, float& d2, float& d3,
    uint32_t a0, uint32_t a1, uint32_t a2, uint32_t a3,
    uint32_t b0, uint32_t b1)
{
    asm volatile(
        "mma.sync.aligned.m16n8k8.row.col.f32.tf32.tf32.f32 "
        "{%0,%1,%2,%3}, {%4,%5,%6,%7}, {%8,%9}, {%0,%1,%2,%3};"
        : "+f"(d0), "+f"(d1), "+f"(d2), "+f"(d3)
        : "r"(a0), "r"(a1), "r"(a2), "r"(a3), "r"(b0), "r"(b1));
}

// row-major [rows][KC] with float4-granule swizzle: granule q of row r lands
// at float offset r*KC + ((q ^ (r & 7)) << 2). Conflict-free for cp.async
// stores AND for ldmatrix (8-row reads hit positions q^0..q^7, all distinct).
static __device__ __forceinline__ uint32_t swz_off(int row, int q) {
    return (uint32_t)(row * KC + (((q ^ (row & 7)) << 2))) * 4u;
}

// ---- pre-pass: W fp32 -> tf32 bits (16MB, ~7us) ----------------------------
__global__ __launch_bounds__(256)
void convert_w_kernel(const float* __restrict__ w)
{
    const int i = blockIdx.x * 256 + threadIdx.x;   // float4 index
    const float4* src = reinterpret_cast<const float4*>(w);
    uint4* dst = reinterpret_cast<uint4*>(g_wtf);
    float4 v = src[i];
    uint4 t;
    t.x = f2tf(v.x); t.y = f2tf(v.y); t.z = f2tf(v.z); t.w = f2tf(v.w);
    dst[i] = t;
}

// ----------------------------------------------------------------------------
__global__ __launch_bounds__(NTHREADS, 3)
void bsl_ldsm_kernel(const float* __restrict__ x,
                     const float* __restrict__ bias,
                     const int*   __restrict__ col_idx,
                     float*       __restrict__ out)
{
    extern __shared__ float smem[];

    const int tid  = threadIdx.x;
    const int wid  = tid >> 5;
    const int lane = tid & 31;
    const int g    = lane >> 2;          // 0..7
    const int cq   = lane & 3;           // 0..3

    const int rb   = blockIdx.x;
    const int tok0 = blockIdx.y * BM;
    const int warp_m = wid * 32;

    int colreg[KBLK];
    #pragma unroll
    for (int i = 0; i < KBLK; ++i) colreg[i] = __ldg(col_idx + rb * KBLK + i);

    const uint32_t smem_u = (uint32_t)__cvta_generic_to_shared(smem);

    const int srow = tid >> 3;           // staging: 16 rows per pass
    const int sq   = tid & 7;            // float4 granule within row

    // ldmatrix per-lane geometry: tile index tl = lane>>3 (0..3)
    const int tl       = lane >> 3;
    const int tl_row   = ((tl & 1) << 3) + (lane & 7);  // +row within 16-row pair
    const int tl_q     = tl >> 1;                       // +granule (0 or 1)

    float acc[2][8][4];
    #pragma unroll
    for (int mt = 0; mt < 2; ++mt)
        #pragma unroll
        for (int nt = 0; nt < 8; ++nt)
            #pragma unroll
            for (int r = 0; r < 4; ++r) acc[mt][nt][r] = 0.0f;

    auto stage = [&](int kc) {
        const int s  = kc % NSTAGE;
        const int cb = kc >> 1;
        const int h  = kc & 1;
        const int c  = colreg[cb];
        const uint32_t Ab = smem_u + (uint32_t)(s * STAGE_FLOATS) * 4u;
        const uint32_t Bb = Ab + (uint32_t)A_BUF * 4u;

        const float* xsrc = x + (size_t)tok0 * IN_F + (size_t)c * BLKSZ + h * KC;
        #pragma unroll
        for (int i = 0; i < 8; ++i) {            // 128 rows
            const int row = srow + i * 16;
            cp16(Ab + swz_off(row, sq), xsrc + (size_t)row * IN_F + sq * 4);
        }
        const uint32_t* wsrc = g_wtf + ((size_t)rb * KBLK + cb) * (BLKSZ * BLKSZ) + h * KC;
        #pragma unroll
        for (int i = 0; i < 4; ++i) {            // 64 rows
            const int row = srow + i * 16;
            cp16(Bb + swz_off(row, sq), wsrc + (size_t)row * BLKSZ + sq * 4);
        }
        cp_commit();
    };

    stage(0);
    stage(1);

    for (int kc = 0; kc < NCHUNK; ++kc) {
        cp_wait<NSTAGE - 2>();
        __syncthreads();   // publish chunk kc; slot (kc+2)%3 consumed by all

        if (kc + NSTAGE - 1 < NCHUNK) stage(kc + NSTAGE - 1);
        else                          cp_commit();   // keep group count exact

        const int s = kc % NSTAGE;
        const uint32_t Abase = smem_u + (uint32_t)(s * STAGE_FLOATS) * 4u;
        const uint32_t Bbase = Abase + (uint32_t)A_BUF * 4u;

        #pragma unroll
        for (int k0 = 0; k0 < KC; k0 += 8) {
            const int qb = (k0 >> 2) + tl_q;     // this lane's granule

            // B fragments: 4 x ldmatrix.x4 (pre-converted tf32 bits)
            uint32_t b[8][2];
            #pragma unroll
            for (int j = 0; j < 4; ++j) {
                const int row = j * 16 + tl_row;
                ldsm4(b[2*j][0], b[2*j+1][0], b[2*j][1], b[2*j+1][1],
                      Bbase + swz_off(row, qb));
            }
            // A fragments: 2 x ldmatrix.x4 (raw x bits) + cvt.rna on regs
            uint32_t a[2][4];
            #pragma unroll
            for (int mt = 0; mt < 2; ++mt) {
                const int row = warp_m + mt * 16 + tl_row;
                ldsm4(a[mt][0], a[mt][1], a[mt][2], a[mt][3],
                      Abase + swz_off(row, qb));
                #pragma unroll
                for (int r = 0; r < 4; ++r)
                    a[mt][r] = f2tf(__uint_as_float(a[mt][r]));
            }
            #pragma unroll
            for (int mt = 0; mt < 2; ++mt)
                #pragma unroll
                for (int nt = 0; nt < 8; ++nt)
                    mma_tf32_16x8x8(acc[mt][nt][0], acc[mt][nt][1],
                                    acc[mt][nt][2], acc[mt][nt][3],
                                    a[mt][0], a[mt][1], a[mt][2], a[mt][3],
                                    b[nt][0], b[nt][1]);
        }
    }

    // ---- epilogue: +bias, store fp32 ----
    const float* bsrc = bias + rb * BLKSZ;
    #pragma unroll
    for (int mt = 0; mt < 2; ++mt) {
        const int row0 = tok0 + warp_m + mt * 16 + g;
        #pragma unroll
        for (int nt = 0; nt < 8; ++nt) {
            const int col = nt * 8 + 2 * cq;
            const float2 bv = *reinterpret_cast<const float2*>(bsrc + col);
            float* d0 = out + (size_t)row0 * OUT_F + rb * BLKSZ + col;
            float* d1 = out + (size_t)(row0 + 8) * OUT_F + rb * BLKSZ + col;
            float2 o0, o1;
            o0.x = acc[mt][nt][0] + bv.x;
            o0.y = acc[mt][nt][1] + bv.y;
            o1.x = acc[mt][nt][2] + bv.x;
            o1.y = acc[mt][nt][3] + bv.y;
            *reinterpret_cast<float2*>(d0) = o0;
            *reinterpret_cast<float2*>(d1) = o1;
        }
    }
}

// ----------------------------------------------------------------------------
extern "C" void kernel_launch(void* const* d_in, const int* in_sizes, int n_in,
                              void* d_out, int out_size)
{
    const float* x = nullptr;
    const float* w = nullptr;
    const float* bias = nullptr;
    const int* row_idx = nullptr;
    const int* col_idx = nullptr;

    for (int i = 0; i < n_in; ++i) {
        long s = (long)in_sizes[i];
        if (s == 8192L * 4096L)          x = (const float*)d_in[i];
        else if (s == 1024L * 64L * 64L) w = (const float*)d_in[i];
        else if (s == 4096L)             bias = (const float*)d_in[i];
        else if (s == 1024L) {
            if (!row_idx) row_idx = (const int*)d_in[i];
            else          col_idx = (const int*)d_in[i];
        }
    }
    if (!x || !w || !bias || !col_idx) {   // positional fallback
        x       = (const float*)d_in[0];
        w       = (const float*)d_in[1];
        bias    = (const float*)d_in[2];
        row_idx = (const int*)d_in[3];
        col_idx = (const int*)d_in[4];
    }
    (void)row_idx; (void)out_size;

    // Pass 1: W -> tf32 bits (1048576 float4s).
    convert_w_kernel<<<W_ELEMS / 4 / 256, 256>>>(w);

    // Pass 2: main GEMM.
    cudaFuncSetAttribute(bsl_ldsm_kernel,
                         cudaFuncAttributeMaxDynamicSharedMemorySize, DYN_SMEM);
    dim3 grid(64, 64);   // x = row-block (fast, shares x via L2), y = token tile
    bsl_ldsm_kernel<<<grid, NTHREADS, DYN_SMEM>>>(x, bias, col_idx, (float*)d_out);
}

// round 12
// speedup vs baseline: 1.3760x; 1.0451x over previous
#include <cuda_runtime.h>
#include <cstdint>

// ----------------------------------------------------------------------------
// BlockSparseLinear: y[8192,4096] = x[8192,4096] @ W^T + bias
// W block-sparse: 64 row-blocks x 16 nonzero 64x64 col-blocks each.
//
// R10: structural only. NSTAGE 3->2 (SMEM 73.7KB -> 49.2KB) => 4 CTAs/SM
// (16 warps, 4 independent barrier domains) to fill each CTA's per-chunk
// barrier-drain window. Single barrier per chunk still sound at depth 2:
// barrier(kc) proves compute(kc-1) done, and stage(kc+1) overwrites slot
// (kc+1)%2 == (kc-1)%2. cp_wait<0> before the barrier; stage right after.
// Inner loop identical to R9 (ldmatrix.x4 fragments; W pre-converted to tf32
// bits; A cvt.rna on regs -> arithmetic unchanged, rel_err must stay 2.935e-4).
// ----------------------------------------------------------------------------

static constexpr int IN_F  = 4096;
static constexpr int OUT_F = 4096;
static constexpr int BLKSZ = 64;
static constexpr int KBLK  = 16;
static constexpr int BM    = 128;          // tokens per CTA
static constexpr int KC    = 32;           // K per chunk (half a col-block)
static constexpr int NCHUNK = KBLK * 2;    // 32
static constexpr int NSTAGE = 2;
static constexpr int NTHREADS = 128;       // 4 warps

static constexpr int A_BUF = BM * KC;          // 4096 floats
static constexpr int B_BUF = BLKSZ * KC;       // 2048 floats
static constexpr int STAGE_FLOATS = A_BUF + B_BUF;              // 6144
static constexpr int DYN_SMEM = NSTAGE * STAGE_FLOATS * 4;      // 49152 B

// Pre-converted W (tf32 bits), same layout as w: [1024][64][64].
static constexpr int W_ELEMS = 1024 * 64 * 64;
__device__ uint32_t g_wtf[W_ELEMS];

static __device__ __forceinline__ uint32_t f2tf(float f) {
    uint32_t u;
    asm("cvt.rna.tf32.f32 %0, %1;" : "=r"(u) : "f"(f));
    return u;
}

static __device__ __forceinline__ void cp16(uint32_t dst_smem, const void* src) {
    asm volatile("cp.async.cg.shared.global [%0], [%1], 16;"
                 :: "r"(dst_smem), "l"(src) : "memory");
}
static __device__ __forceinline__ void cp_commit() {
    asm volatile("cp.async.commit_group;" ::: "memory");
}
template <int N>
static __device__ __forceinline__ void cp_wait() {
    asm volatile("cp.async.wait_group %0;" :: "n"(N) : "memory");
}

static __device__ __forceinline__ void ldsm4(uint32_t& r0, uint32_t& r1,
                                             uint32_t& r2, uint32_t& r3,
                                             uint32_t addr) {
    asm volatile("ldmatrix.sync.aligned.m8n8.x4.shared.b16 {%0,%1,%2,%3}, [%4];"
                 : "=r"(r0), "=r"(r1), "=r"(r2), "=r"(r3) : "r"(addr));
}

static __device__ __forceinline__ void mma_tf32_16x8x8(
    float& d0, float& d1, float& d2, float& d3,
    uint32_t a0, uint32_t a1, uint32_t a2, uint32_t a3,
    uint32_t b0, uint32_t b1)
{
    asm volatile(
        "mma.sync.aligned.m16n8k8.row.col.f32.tf32.tf32.f32 "
        "{%0,%1,%2,%3}, {%4,%5,%6,%7}, {%8,%9}, {%0,%1,%2,%3};"
        : "+f"(d0), "+f"(d1), "+f"(d2), "+f"(d3)
        : "r"(a0), "r"(a1), "r"(a2), "r"(a3), "r"(b0), "r"(b1));
}

// row-major [rows][KC] with float4-granule swizzle: granule q of row r lands
// at float offset r*KC + ((q ^ (r & 7)) << 2). Conflict-free for cp.async
// stores AND for ldmatrix (8-row reads hit positions q^0..q^7, all distinct).
static __device__ __forceinline__ uint32_t swz_off(int row, int q) {
    return (uint32_t)(row * KC + (((q ^ (row & 7)) << 2))) * 4u;
}

// ---- pre-pass: W fp32 -> tf32 bits (16MB, ~7us) ----------------------------
__global__ __launch_bounds__(256)
void convert_w_kernel(const float* __restrict__ w)
{
    const int i = blockIdx.x * 256 + threadIdx.x;   // float4 index
    const float4* src = reinterpret_cast<const float4*>(w);
    uint4* dst = reinterpret_cast<uint4*>(g_wtf);
    float4 v = src[i];
    uint4 t;
    t.x = f2tf(v.x); t.y = f2tf(v.y); t.z = f2tf(v.z); t.w = f2tf(v.w);
    dst[i] = t;
}

// ----------------------------------------------------------------------------
__global__ __launch_bounds__(NTHREADS, 4)
void bsl_ldsm_kernel(const float* __restrict__ x,
                     const float* __restrict__ bias,
                     const int*   __restrict__ col_idx,
                     float*       __restrict__ out)
{
    extern __shared__ float smem[];

    const int tid  = threadIdx.x;
    const int wid  = tid >> 5;
    const int lane = tid & 31;
    const int g    = lane >> 2;          // 0..7
    const int cq   = lane & 3;           // 0..3

    const int rb   = blockIdx.x;
    const int tok0 = blockIdx.y * BM;
    const int warp_m = wid * 32;

    int colreg[KBLK];
    #pragma unroll
    for (int i = 0; i < KBLK; ++i) colreg[i] = __ldg(col_idx + rb * KBLK + i);

    const uint32_t smem_u = (uint32_t)__cvta_generic_to_shared(smem);

    const int srow = tid >> 3;           // staging: 16 rows per pass
    const int sq   = tid & 7;            // float4 granule within row

    // ldmatrix per-lane geometry: tile index tl = lane>>3 (0..3)
    const int tl       = lane >> 3;
    const int tl_row   = ((tl & 1) << 3) + (lane & 7);  // +row within 16-row pair
    const int tl_q     = tl >> 1;                       // +granule (0 or 1)

    float acc[2][8][4];
    #pragma unroll
    for (int mt = 0; mt < 2; ++mt)
        #pragma unroll
        for (int nt = 0; nt < 8; ++nt)
            #pragma unroll
            for (int r = 0; r < 4; ++r) acc[mt][nt][r] = 0.0f;

    auto stage = [&](int kc) {
        const int s  = kc % NSTAGE;
        const int cb = kc >> 1;
        const int h  = kc & 1;
        const int c  = colreg[cb];
        const uint32_t Ab = smem_u + (uint32_t)(s * STAGE_FLOATS) * 4u;
        const uint32_t Bb = Ab + (uint32_t)A_BUF * 4u;

        const float* xsrc = x + (size_t)tok0 * IN_F + (size_t)c * BLKSZ + h * KC;
        #pragma unroll
        for (int i = 0; i < 8; ++i) {            // 128 rows
            const int row = srow + i * 16;
            cp16(Ab + swz_off(row, sq), xsrc + (size_t)row * IN_F + sq * 4);
        }
        const uint32_t* wsrc = g_wtf + ((size_t)rb * KBLK + cb) * (BLKSZ * BLKSZ) + h * KC;
        #pragma unroll
        for (int i = 0; i < 4; ++i) {            // 64 rows
            const int row = srow + i * 16;
            cp16(Bb + swz_off(row, sq), wsrc + (size_t)row * BLKSZ + sq * 4);
        }
        cp_commit();
    };

    stage(0);

    for (int kc = 0; kc < NCHUNK; ++kc) {
        cp_wait<0>();      // chunk kc landed (only group pending here)
        __syncthreads();   // publish chunk kc; proves compute(kc-1) done by all
                           // -> slot (kc+1)%2 == (kc-1)%2 is free to restage

        if (kc + 1 < NCHUNK) stage(kc + 1);

        const int s = kc % NSTAGE;
        const uint32_t Abase = smem_u + (uint32_t)(s * STAGE_FLOATS) * 4u;
        const uint32_t Bbase = Abase + (uint32_t)A_BUF * 4u;

        #pragma unroll
        for (int k0 = 0; k0 < KC; k0 += 8) {
            const int qb = (k0 >> 2) + tl_q;     // this lane's granule

            // B fragments: 4 x ldmatrix.x4 (pre-converted tf32 bits)
            uint32_t b[8][2];
            #pragma unroll
            for (int j = 0; j < 4; ++j) {
                const int row = j * 16 + tl_row;
                ldsm4(b[2*j][0], b[2*j+1][0], b[2*j][1], b[2*j+1][1],
                      Bbase + swz_off(row, qb));
            }
            // A fragments: 2 x ldmatrix.x4 (raw x bits) + cvt.rna on regs
            uint32_t a[2][4];
            #pragma unroll
            for (int mt = 0; mt < 2; ++mt) {
                const int row = warp_m + mt * 16 + tl_row;
                ldsm4(a[mt][0], a[mt][1], a[mt][2], a[mt][3],
                      Abase + swz_off(row, qb));
                #pragma unroll
                for (int r = 0; r < 4; ++r)
                    a[mt][r] = f2tf(__uint_as_float(a[mt][r]));
            }
            #pragma unroll
            for (int mt = 0; mt < 2; ++mt)
                #pragma unroll
                for (int nt = 0; nt < 8; ++nt)
                    mma_tf32_16x8x8(acc[mt][nt][0], acc[mt][nt][1],
                                    acc[mt][nt][2], acc[mt][nt][3],
                                    a[mt][0], a[mt][1], a[mt][2], a[mt][3],
                                    b[nt][0], b[nt][1]);
        }
    }

    // ---- epilogue: +bias, store fp32 ----
    const float* bsrc = bias + rb * BLKSZ;
    #pragma unroll
    for (int mt = 0; mt < 2; ++mt) {
        const int row0 = tok0 + warp_m + mt * 16 + g;
        #pragma unroll
        for (int nt = 0; nt < 8; ++nt) {
            const int col = nt * 8 + 2 * cq;
            const float2 bv = *reinterpret_cast<const float2*>(bsrc + col);
            float* d0 = out + (size_t)row0 * OUT_F + rb * BLKSZ + col;
            float* d1 = out + (size_t)(row0 + 8) * OUT_F + rb * BLKSZ + col;
            float2 o0, o1;
            o0.x = acc[mt][nt][0] + bv.x;
            o0.y = acc[mt][nt][1] + bv.y;
            o1.x = acc[mt][nt][2] + bv.x;
            o1.y = acc[mt][nt][3] + bv.y;
            *reinterpret_cast<float2*>(d0) = o0;
            *reinterpret_cast<float2*>(d1) = o1;
        }
    }
}

// ----------------------------------------------------------------------------
extern "C" void kernel_launch(void* const* d_in, const int* in_sizes, int n_in,
                              void* d_out, int out_size)
{
    const float* x = nullptr;
    const float* w = nullptr;
    const float* bias = nullptr;
    const int* row_idx = nullptr;
    const int* col_idx = nullptr;

    for (int i = 0; i < n_in; ++i) {
        long s = (long)in_sizes[i];
        if (s == 8192L * 4096L)          x = (const float*)d_in[i];
        else if (s == 1024L * 64L * 64L) w = (const float*)d_in[i];
        else if (s == 4096L)             bias = (const float*)d_in[i];
        else if (s == 1024L) {
            if (!row_idx) row_idx = (const int*)d_in[i];
            else          col_idx = (const int*)d_in[i];
        }
    }
    if (!x || !w || !bias || !col_idx) {   // positional fallback
        x       = (const float*)d_in[0];
        w       = (const float*)d_in[1];
        bias    = (const float*)d_in[2];
        row_idx = (const int*)d_in[3];
        col_idx = (const int*)d_in[4];
    }
    (void)row_idx; (void)out_size;

    // Pass 1: W -> tf32 bits (1048576 float4s).
    convert_w_kernel<<<W_ELEMS / 4 / 256, 256>>>(w);

    // Pass 2: main GEMM.
    cudaFuncSetAttribute(bsl_ldsm_kernel,
                         cudaFuncAttributeMaxDynamicSharedMemorySize, DYN_SMEM);
    dim3 grid(64, 64);   // x = row-block (fast, shares x via L2), y = token tile
    bsl_ldsm_kernel<<<grid, NTHREADS, DYN_SMEM>>>(x, bias, col_idx, (float*)d_out);
}